// round 17
// baseline (speedup 1.0000x reference)
#include <cuda_runtime.h>

// QLSTM on GB300 — R17: transfer-matrix with WARP SPECIALIZATION.
// 8 warps/CTA: warps 0-3 = Rm role (circuit c): preact+g tables, masked
// prefix chain (lanes 0-15), E_0/E_9 live reduces, even-w combines, LSTM.
// warps 4-7 = L role (circuit c): K-contracted 2-term suffix chain
// (lanes 0-15), odd-w combines. Named barrier (1+c, 64) pairs the two warps
// of a circuit; one __syncthreads per step for the qpart exchange.

#define TT 64
#define BB 256
#define DD 32
#define HH 10
#define NTH 256

struct Smem {
    float2 sRm[4][10][16];      // Rm snapshots w=1..8 (+ setup scratch)
    float2 sL[4][10][16];       // L snapshots w=1..8 (+ setup scratch)
    float2 sG[4][HH][4];        // per-circuit per-wire g tables (step-dep)
    float2 sN[HH][4];           // N_j = U_j^dag Z U_j (fixed)
    float2 sK[16];              // boundary kernel
    float4 sU0[HH];             // layer-1 gate (ax,ay,bx,by)
    float  sWx[TT][40];         // 0.5*(W.x + b) all steps
    float  sWh[4][HH][HH];      // 0.5*W_h
    float  qpart[2][4][HH];
};

__device__ __forceinline__ float2 cmul(float2 a, float2 b) {
    return make_float2(a.x*b.x - a.y*b.y, a.x*b.y + a.y*b.x);
}
__device__ __forceinline__ float2 cmulc(float2 a, float2 b) {   // conj(a)*b
    return make_float2(a.x*b.x + a.y*b.y, a.x*b.y - a.y*b.x);
}
__device__ __forceinline__ float2 cfma(float2 a, float2 b, float2 acc) {
    acc.x = fmaf(a.x, b.x, fmaf(-a.y, b.y, acc.x));
    acc.y = fmaf(a.x, b.y, fmaf( a.y, b.x, acc.y));
    return acc;
}
__device__ __forceinline__ float fast_tanh(float x) {
    float r;
    asm("tanh.approx.f32 %0, %1;" : "=f"(r) : "f"(x));
    return r;
}
__device__ __forceinline__ float fast_sigmoid(float x) {
    return fmaf(0.5f, fast_tanh(0.5f * x), 0.5f);
}
__device__ __forceinline__ void cpair_bar(int c) {
    asm volatile("bar.sync %0, 64;" :: "r"(c + 1) : "memory");
}

__global__ void __launch_bounds__(NTH, 2)
qlstm_kernel(const float* __restrict__ inputs,
             const float* __restrict__ qparams,
             const float* __restrict__ Wf, const float* __restrict__ bf,
             const float* __restrict__ Wi, const float* __restrict__ bi,
             const float* __restrict__ Wg, const float* __restrict__ bg,
             const float* __restrict__ Wo, const float* __restrict__ bo,
             float* __restrict__ out)
{
    extern __shared__ char smem_raw[];
    Smem* S = (Smem*)smem_raw;

    const int tid  = threadIdx.x;
    const int b    = blockIdx.x;
    const int wid  = tid >> 5;        // 0..7
    const int c    = wid & 3;         // circuit
    const int role = wid >> 2;        // 0: Rm, 1: L
    const int lane = tid & 31;
    const int row  = (lane >> 2) & 3;
    const int col  = lane & 3;

    const float* Ws[4] = {Wf, Wi, Wg, Wo};
    const float* Bs[4] = {bf, bi, bg, bo};

    // ---- setup phase 1: stage x into scratch (sRm+sL region), gate consts --
    float* scratch = (float*)&S->sRm[0][0][0];   // 1280 float2 >= 2048 floats
    for (int i = tid; i < TT * DD; i += NTH)
        scratch[i] = inputs[((size_t)(i / DD) * BB + b) * DD + (i % DD)];

    if (tid < 20) {
        int l = tid / 10, w = tid % 10;
        float tz = qparams[(l*10 + w)*3 + 0];
        float tx = qparams[(l*10 + w)*3 + 1];
        float ty = qparams[(l*10 + w)*3 + 2];
        float c1, s1, c2, s2, c3, s3;
        __sincosf(0.5f*tz, &s1, &c1);
        __sincosf(0.5f*tx, &s2, &c2);
        __sincosf(0.5f*ty, &s3, &c3);
        float aAx =  c2*c1, aAy = -c2*s1;   // RX*RZ
        float bAx = -s2*s1, bAy = -s2*c1;
        float ax = c3*aAx - s3*bAx, ay = c3*aAy - s3*bAy;   // U = RY*RX*RZ
        float bx = s3*aAx + c3*bAx, by = s3*aAy + c3*bAy;
        if (l == 0) {
            S->sU0[w] = make_float4(ax, ay, bx, by);
        } else {
            float n00 = ax*ax + ay*ay - bx*bx - by*by;
            float pr  = ax*bx - ay*by;
            float pi_ = ax*by + ay*bx;
            S->sN[w][0] = make_float2( n00, 0.f);
            S->sN[w][1] = make_float2(-2.f*pr,  2.f*pi_);
            S->sN[w][2] = make_float2(-2.f*pr, -2.f*pi_);
            S->sN[w][3] = make_float2(-n00, 0.f);
        }
    }
    __syncthreads();

    // ---- setup phase 2: 0.5*(W.x + b); W_h; K ----
    if (tid < 120) {
        const int trio = tid / 40, pr = tid % 40;
        const int g = pr / 10, h = pr % 10;
        const float* Wrow = Ws[g] + h * 42;
        const float bias = Bs[g][h];
        float wreg[DD];
#pragma unroll
        for (int j = 0; j < DD; ++j) wreg[j] = Wrow[j];
        const int t0 = (trio == 0) ? 0 : (trio == 1) ? 22 : 44;
        const int t1 = (trio == 0) ? 22 : (trio == 1) ? 44 : TT;
        for (int t = t0; t < t1; ++t) {
            const float* xv = scratch + t * DD;
            float a0 = 0.f, a1 = 0.f, a2 = 0.f, a3 = 0.f;
#pragma unroll
            for (int j = 0; j < DD; j += 4) {
                a0 = fmaf(wreg[j],   xv[j],   a0);
                a1 = fmaf(wreg[j+1], xv[j+1], a1);
                a2 = fmaf(wreg[j+2], xv[j+2], a2);
                a3 = fmaf(wreg[j+3], xv[j+3], a3);
            }
            S->sWx[t][pr] = 0.5f * (((a0 + a1) + (a2 + a3)) + bias);
        }
    }
    if (tid < 40) {
        const int g = tid / 10, h = tid % 10;
        const float* Wrow = Ws[g] + h * 42 + DD;
#pragma unroll
        for (int j = 0; j < HH; ++j)
            S->sWh[g][h][j] = 0.5f * Wrow[j];
    }
    if (tid < 16) {
        int r = tid >> 2, cc = tid & 3;
        int idx = (((cc >> 1) ^ (r >> 1)) << 1) | ((cc & 1) ^ (r & 1));
        S->sK[tid] = S->sN[0][idx];
    }
    const bool e0_mask = (col == row) || (col == (row ^ 3));

    float cx_reg = 0.f, hx_reg = 0.f;
    __syncthreads();

    for (int t = 0; t < TT; ++t) {
        const int par = t & 1;

        // ---- role 0: pre-activation (h-part) -> g tables (lanes 0-9) ----
        if (role == 0) {
            float hj[HH];
#pragma unroll
            for (int j = 0; j < HH; ++j)
                hj[j] = __shfl_sync(0xffffffffu, hx_reg, j);
            if (lane < HH) {
                float acc0 = S->sWx[t][c * 10 + lane], acc1 = 0.f;
                const float* wh = S->sWh[c][lane];
#pragma unroll
                for (int j = 0; j < HH; j += 2) {
                    acc0 = fmaf(wh[j],   hj[j],   acc0);
                    acc1 = fmaf(wh[j+1], hj[j+1], acc1);
                }
                float cc, ss;
                __sincosf(acc0 + acc1, &ss, &cc);
                float4 U = S->sU0[lane];
                float2 v0 = make_float2(U.x*cc - U.z*ss, U.y*cc + U.w*ss);
                float2 v1 = make_float2(U.z*cc + U.x*ss, U.w*cc - U.y*ss);
                S->sG[c][lane][0] = cmulc(v0, v0);
                S->sG[c][lane][1] = cmulc(v0, v1);
                S->sG[c][lane][2] = cmulc(v1, v0);
                S->sG[c][lane][3] = cmulc(v1, v1);
            }
        }
        cpair_bar(c);    // g tables ready for both role warps of circuit c

        // ---- chains (lanes 0-15 of each warp) ----
        if (lane < 16) {
            if (role == 0) {
                // fused init: Rm_1[r,c] = N_1[r] * g_1[r^c] * g_0[c]
                float2 R = cmul(S->sN[1][row],
                                cmul(S->sG[c][1][row ^ col], S->sG[c][0][col]));
                S->sRm[c][1][lane] = R;
#pragma unroll
                for (int i = 0; i < 8; ++i) {
                    const int j = i + 2;
                    const float2* gj = S->sG[c][j];
                    float2 cf0 = gj[row], cf1 = gj[row ^ 1];
                    float2 cf2 = gj[row ^ 2], cf3 = gj[row ^ 3];
                    float2 o0, o1, o2, o3;
                    o0.x = __shfl_sync(0xffffu, R.x, col);
                    o0.y = __shfl_sync(0xffffu, R.y, col);
                    o1.x = __shfl_sync(0xffffu, R.x, 4 + col);
                    o1.y = __shfl_sync(0xffffu, R.y, 4 + col);
                    o2.x = __shfl_sync(0xffffu, R.x, 8 + col);
                    o2.y = __shfl_sync(0xffffu, R.y, 8 + col);
                    o3.x = __shfl_sync(0xffffu, R.x, 12 + col);
                    o3.y = __shfl_sync(0xffffu, R.y, 12 + col);
                    float2 acc = cfma(cf0, o0, cfma(cf1, o1,
                                 cfma(cf2, o2, cmul(cf3, o3))));
                    R = cmul(S->sN[j][row], acc);
                    if (i < 7) S->sRm[c][j][lane] = R;   // Rm_9 stays live
                }
                // E_0 masked reduce + E_9 K-dot on live Rm_9
                float e0 = e0_mask ? R.x : 0.f;
                float2 Kv = S->sK[lane];
                float e9 = fmaf(Kv.x, R.x, -Kv.y * R.y);
#pragma unroll
                for (int d = 1; d < 16; d <<= 1) {
                    e0 += __shfl_xor_sync(0xffffu, e0, d);
                    e9 += __shfl_xor_sync(0xffffu, e9, d);
                }
                if (lane == 0) {
                    S->qpart[par][c][0] = e0;
                    S->qpart[par][c][9] = e9;
                }
            } else {
                // L chain: L_9 = K;  L_{w-1}[t,c] = g_w[t] L_w[0,c] + g_w[t^3] L_w[3,c]
                float2 R = S->sK[lane];
#pragma unroll
                for (int i = 0; i < 8; ++i) {
                    const int j = 9 - i;
                    const float2* gj = S->sG[c][j];
                    float2 cf0 = gj[row], cf1 = gj[row ^ 3];
                    float2 o0, o1;
                    o0.x = __shfl_sync(0xffffu, R.x, col);
                    o0.y = __shfl_sync(0xffffu, R.y, col);
                    o1.x = __shfl_sync(0xffffu, R.x, 12 + col);
                    o1.y = __shfl_sync(0xffffu, R.y, 12 + col);
                    R = cfma(cf0, o0, cmul(cf1, o1));
                    S->sL[c][j - 1][lane] = R;          // L_8 .. L_1
                }
            }
        }
        cpair_bar(c);    // both snapshot sets ready

        // ---- combine: E_w = Re sum_ln L_w[ln] * Rm_w[ln] ----
        if (lane < 16) {
#pragma unroll
            for (int k = 0; k < 4; ++k) {
                const int w = (role == 0) ? (2 + 2*k) : (1 + 2*k);
                float2 L  = S->sL[c][w][lane];
                float2 rm = S->sRm[c][w][lane];
                float e = fmaf(L.x, rm.x, -L.y * rm.y);
#pragma unroll
                for (int d = 1; d < 16; d <<= 1)
                    e += __shfl_xor_sync(0xffffu, e, d);
                if (lane == 0)
                    S->qpart[par][c][w] = e;
            }
        }
        __syncthreads();

        // ---- LSTM cell update (role-0 warps, lanes 0-9, redundant) ----
        if (role == 0 && lane < HH) {
            const int h = lane;
            float qf = S->qpart[par][0][h];
            float qi = S->qpart[par][1][h];
            float qg = S->qpart[par][2][h];
            float qo = S->qpart[par][3][h];
            float fg = fast_sigmoid(qf);
            float ig = fast_sigmoid(qi);
            float gg = fast_tanh(qg);
            float og = fast_sigmoid(qo);
            cx_reg = fg * cx_reg + ig * gg;
            hx_reg = og * fast_tanh(cx_reg);
            if (c == 0)
                out[((size_t)(t*BB) + b)*HH + h] = hx_reg;
        }
    }

    if (wid == 0 && lane < HH) {
        out[(size_t)TT*BB*HH + (size_t)b*HH + lane]                 = hx_reg;
        out[(size_t)TT*BB*HH + (size_t)BB*HH + (size_t)b*HH + lane] = cx_reg;
    }
}

extern "C" void kernel_launch(void* const* d_in, const int* in_sizes, int n_in,
                              void* d_out, int out_size) {
    (void)in_sizes; (void)n_in; (void)out_size;
    const float* inputs  = (const float*)d_in[0];
    const float* qparams = (const float*)d_in[1];
    const float* Wf = (const float*)d_in[2];
    const float* bf = (const float*)d_in[3];
    const float* Wi = (const float*)d_in[4];
    const float* bi = (const float*)d_in[5];
    const float* Wg = (const float*)d_in[6];
    const float* bg = (const float*)d_in[7];
    const float* Wo = (const float*)d_in[8];
    const float* bo = (const float*)d_in[9];
    float* out = (float*)d_out;
    cudaFuncSetAttribute(qlstm_kernel,
                         cudaFuncAttributeMaxDynamicSharedMemorySize,
                         (int)sizeof(Smem));
    qlstm_kernel<<<BB, NTH, sizeof(Smem)>>>(inputs, qparams, Wf, bf, Wi, bi,
                                            Wg, bg, Wo, bo, out);
}